// round 3
// baseline (speedup 1.0000x reference)
#include <cuda_runtime.h>

// Problem constants
#define EPSV 0.007f
#define NB   32     // batch
#define CI   128    // in channels
#define HI   56
#define WI   56
#define CO   256    // out channels (both stages)
#define HO   28
#define WO   28
#define C2   256    // stage-B in channels

// ---------------- scratch (static device memory; no allocations) ----------
__device__ float g_y[(size_t)NB * CO * HO * WO];        // YAT output, 25.7 MB
__device__ float g_wyat_t[CI * 9 * CO];                 // [ (ci*9+tap) ][ co ]
__device__ float g_wlin_t[C2 * 9 * CO];
__device__ float g_wsh_t[CI * CO];
__device__ float g_wsq[CO];

// ---------------- weight prep (transpose for coalesced smem fills) --------
__global__ void prep_yat(const float* __restrict__ w) {
    int k  = blockIdx.x;        // 0..1151  (ci*9+tap)
    int co = threadIdx.x;       // 0..255
    g_wyat_t[k * CO + co] = w[co * 1152 + k];
}
__global__ void prep_lin(const float* __restrict__ w) {
    int k  = blockIdx.x;        // 0..2303
    int co = threadIdx.x;
    g_wlin_t[k * CO + co] = w[co * 2304 + k];
}
__global__ void prep_sh(const float* __restrict__ w) {
    int k  = blockIdx.x;        // 0..127
    int co = threadIdx.x;
    g_wsh_t[k * CO + co] = w[co * CI + k];
}
__global__ void prep_wsq(const float* __restrict__ w) {
    __shared__ float red[128];
    int co = blockIdx.x;
    float s = 0.f;
    for (int k = threadIdx.x; k < 1152; k += 128) {
        float v = w[co * 1152 + k];
        s += v * v;
    }
    red[threadIdx.x] = s;
    __syncthreads();
    for (int off = 64; off > 0; off >>= 1) {
        if (threadIdx.x < off) red[threadIdx.x] += red[threadIdx.x + off];
        __syncthreads();
    }
    if (threadIdx.x == 0) g_wsq[co] = red[0];
}

// ---------------- Stage A: YAT conv (stride-2 3x3) + fused 1x1 shortcut ---
// Block: 64 co x 2 output rows x 28 px. 128 threads.
// Thread: 4 co x 7 px x 1 row.
__global__ __launch_bounds__(128)
void yat_kernel(const float* __restrict__ x, const float* __restrict__ alpha,
                float* __restrict__ out_id) {
    __shared__ __align__(16) float xs[8][5][58];     // [ci][row][col+1pad]
    __shared__ __align__(16) float ws[8 * 9][64];    // [ci*9+tap][co]
    __shared__ __align__(16) float wsh[8][64];       // [ci][co]

    const int tid   = threadIdx.x;
    const int co_b  = blockIdx.x;   // 0..3   (64-co group)
    const int h_b   = blockIdx.y;   // 0..13  (2 output rows)
    const int n     = blockIdx.z;   // 0..31
    const int co_t  = tid & 15;             // 4 co each
    const int px_t  = (tid >> 4) & 3;       // 7 px each (pw = px_t + 4j)
    const int row_t = tid >> 6;             // output row h0+row_t

    float acc[28], ida[28], psq[7];
#pragma unroll
    for (int i = 0; i < 28; i++) { acc[i] = 0.f; ida[i] = 0.f; }
#pragma unroll
    for (int j = 0; j < 7; j++) psq[j] = 0.f;

    const float* xbase = x + (size_t)n * CI * HI * WI;
    const int gr0 = 4 * h_b - 1;    // first input row needed

    for (int ci0 = 0; ci0 < CI; ci0 += 8) {
        __syncthreads();
        // fill xs: 8 ci x 5 rows x 58 cols (zero-padded)
        for (int idx = tid; idx < 8 * 5 * 58; idx += 128) {
            int cc  = idx / 290;
            int rem = idx - cc * 290;
            int r   = rem / 58;
            int c   = rem - r * 58;
            int gr  = gr0 + r;
            int gc  = c - 1;
            float v = 0.f;
            if (gr >= 0 && gr < HI && gc >= 0 && gc < WI)
                v = xbase[((ci0 + cc) * HI + gr) * WI + gc];
            xs[cc][r][c] = v;
        }
        // fill ws (coalesced gmem, conflict-free STS)
        for (int idx = tid; idx < 8 * 9 * 64; idx += 128) {
            int rr = idx >> 6;
            int co = idx & 63;
            ws[rr][co] = g_wyat_t[(ci0 * 9 + rr) * CO + co_b * 64 + co];
        }
        // fill shortcut weights
        for (int idx = tid; idx < 8 * 64; idx += 128) {
            int cc = idx >> 6;
            int co = idx & 63;
            wsh[cc][co] = g_wsh_t[(ci0 + cc) * CO + co_b * 64 + co];
        }
        __syncthreads();

#pragma unroll
        for (int cc = 0; cc < 8; cc++) {
#pragma unroll
            for (int kh = 0; kh < 3; kh++) {
                const int r = 2 * row_t + kh;
#pragma unroll
                for (int kw = 0; kw < 3; kw++) {
                    float xv[7];
#pragma unroll
                    for (int j = 0; j < 7; j++)
                        xv[j] = xs[cc][r][2 * (px_t + 4 * j) + kw];
                    float4 w4 = *(const float4*)&ws[cc * 9 + kh * 3 + kw][co_t * 4];
#pragma unroll
                    for (int j = 0; j < 7; j++) {
                        acc[0 * 7 + j] += w4.x * xv[j];
                        acc[1 * 7 + j] += w4.y * xv[j];
                        acc[2 * 7 + j] += w4.z * xv[j];
                        acc[3 * 7 + j] += w4.w * xv[j];
                        psq[j] += xv[j] * xv[j];
                    }
                    if (kh == 1 && kw == 1) {      // center tap = 1x1 stride-2 shortcut
                        float4 s4 = *(const float4*)&wsh[cc][co_t * 4];
#pragma unroll
                        for (int j = 0; j < 7; j++) {
                            ida[0 * 7 + j] += s4.x * xv[j];
                            ida[1 * 7 + j] += s4.y * xv[j];
                            ida[2 * 7 + j] += s4.z * xv[j];
                            ida[3 * 7 + j] += s4.w * xv[j];
                        }
                    }
                }
            }
        }
    }

    // epilogue: y = scale * dot^2 / (|patch|^2 + |w|^2 - 2 dot + eps)
    const float scale = powf(16.0f / logf(257.0f), alpha[0]);
    const int h = 2 * h_b + row_t;
#pragma unroll
    for (int i = 0; i < 4; i++) {
        const int co = co_b * 64 + co_t * 4 + i;
        const float wq = g_wsq[co];
        const size_t base = (((size_t)n * CO + co) * HO + h) * WO;
#pragma unroll
        for (int j = 0; j < 7; j++) {
            const int pw = px_t + 4 * j;
            const float dot = acc[i * 7 + j];
            const float d = psq[j] + wq - 2.f * dot + EPSV;
            g_y[base + pw] = scale * dot * dot / d;
            out_id[base + pw] = ida[i * 7 + j];   // identity term, added in stage B
        }
    }
}

// ---------------- Stage B: 3x3 stride-1 conv over g_y, += identity -------
__global__ __launch_bounds__(128)
void lin_kernel(float* __restrict__ out) {
    __shared__ __align__(16) float ys[8][4][30];
    __shared__ __align__(16) float ws[8 * 9][64];

    const int tid   = threadIdx.x;
    const int co_b  = blockIdx.x;
    const int h_b   = blockIdx.y;
    const int n     = blockIdx.z;
    const int co_t  = tid & 15;
    const int px_t  = (tid >> 4) & 3;
    const int row_t = tid >> 6;

    float acc[28];
#pragma unroll
    for (int i = 0; i < 28; i++) acc[i] = 0.f;

    const int h0 = 2 * h_b;

    for (int ci0 = 0; ci0 < C2; ci0 += 8) {
        __syncthreads();
        for (int idx = tid; idx < 8 * 4 * 30; idx += 128) {
            int cc  = idx / 120;
            int rem = idx - cc * 120;
            int r   = rem / 30;
            int c   = rem - r * 30;
            int gr  = h0 - 1 + r;
            int gc  = c - 1;
            float v = 0.f;
            if (gr >= 0 && gr < HO && gc >= 0 && gc < WO)
                v = g_y[(((size_t)n * C2 + ci0 + cc) * HO + gr) * WO + gc];
            ys[cc][r][c] = v;
        }
        for (int idx = tid; idx < 8 * 9 * 64; idx += 128) {
            int rr = idx >> 6;
            int co = idx & 63;
            ws[rr][co] = g_wlin_t[(ci0 * 9 + rr) * CO + co_b * 64 + co];
        }
        __syncthreads();

#pragma unroll
        for (int cc = 0; cc < 8; cc++) {
#pragma unroll
            for (int kh = 0; kh < 3; kh++) {
                const int r = row_t + kh;
#pragma unroll
                for (int kw = 0; kw < 3; kw++) {
                    float4 w4 = *(const float4*)&ws[cc * 9 + kh * 3 + kw][co_t * 4];
#pragma unroll
                    for (int j = 0; j < 7; j++) {
                        float xv = ys[cc][r][px_t + 4 * j + kw];
                        acc[0 * 7 + j] += w4.x * xv;
                        acc[1 * 7 + j] += w4.y * xv;
                        acc[2 * 7 + j] += w4.z * xv;
                        acc[3 * 7 + j] += w4.w * xv;
                    }
                }
            }
        }
    }

    const int h = h0 + row_t;
#pragma unroll
    for (int i = 0; i < 4; i++) {
        const int co = co_b * 64 + co_t * 4 + i;
        const size_t base = (((size_t)n * CO + co) * HO + h) * WO;
#pragma unroll
        for (int j = 0; j < 7; j++) {
            const int pw = px_t + 4 * j;
            out[base + pw] = acc[i * 7 + j] + out[base + pw];  // += identity
        }
    }
}

// ---------------- launch ---------------------------------------------------
extern "C" void kernel_launch(void* const* d_in, const int* in_sizes, int n_in,
                              void* d_out, int out_size) {
    const float* x       = (const float*)d_in[0];
    const float* w_yat   = (const float*)d_in[1];
    const float* alpha   = (const float*)d_in[2];
    const float* w_lin   = (const float*)d_in[3];
    const float* w_short = (const float*)d_in[4];
    float* out = (float*)d_out;

    prep_yat<<<CI * 9, CO>>>(w_yat);
    prep_lin<<<C2 * 9, CO>>>(w_lin);
    prep_sh<<<CI, CO>>>(w_short);
    prep_wsq<<<CO, 128>>>(w_yat);

    dim3 grid(4, 14, NB);           // co-groups x row-pairs x batch
    yat_kernel<<<grid, 128>>>(x, alpha, out);
    lin_kernel<<<grid, 128>>>(out);
}

// round 4
// speedup vs baseline: 1.0132x; 1.0132x over previous
#include <cuda_runtime.h>

// Problem constants
#define EPSV 0.007f
#define NB   32     // batch
#define CI   128    // in channels
#define HI   56
#define WI   56
#define CO   256    // out channels (both stages)
#define HO   28
#define WO   28
#define C2   256    // stage-B in channels

// ---------------- scratch (static device memory; no allocations) ----------
__device__ float g_y[(size_t)NB * CO * HO * WO];        // YAT output, 25.7 MB
__device__ float g_wyat_t[CI * 9 * CO];                 // [ (ci*9+tap) ][ co ]
__device__ float g_wlin_t[C2 * 9 * CO];
__device__ float g_wsh_t[CI * CO];
__device__ float g_wsq[CO];

// ---------------- weight prep (transpose for coalesced smem fills) --------
__global__ void prep_yat(const float* __restrict__ w) {
    int k  = blockIdx.x;        // 0..1151  (ci*9+tap)
    int co = threadIdx.x;       // 0..255
    g_wyat_t[k * CO + co] = w[co * 1152 + k];
}
__global__ void prep_lin(const float* __restrict__ w) {
    int k  = blockIdx.x;        // 0..2303
    int co = threadIdx.x;
    g_wlin_t[k * CO + co] = w[co * 2304 + k];
}
__global__ void prep_sh(const float* __restrict__ w) {
    int k  = blockIdx.x;        // 0..127
    int co = threadIdx.x;
    g_wsh_t[k * CO + co] = w[co * CI + k];
}
__global__ void prep_wsq(const float* __restrict__ w) {
    __shared__ float red[128];
    int co = blockIdx.x;
    float s = 0.f;
    for (int k = threadIdx.x; k < 1152; k += 128) {
        float v = w[co * 1152 + k];
        s += v * v;
    }
    red[threadIdx.x] = s;
    __syncthreads();
    for (int off = 64; off > 0; off >>= 1) {
        if (threadIdx.x < off) red[threadIdx.x] += red[threadIdx.x + off];
        __syncthreads();
    }
    if (threadIdx.x == 0) g_wsq[co] = red[0];
}

// ---------------- Stage A: YAT conv (stride-2 3x3) + fused 1x1 shortcut ---
// Block: 64 co x 2 output rows x 28 px. 128 threads.
// Thread: 4 co x 7 px x 1 row.
__global__ __launch_bounds__(128)
void yat_kernel(const float* __restrict__ x, const float* __restrict__ alpha,
                float* __restrict__ out_id) {
    __shared__ __align__(16) float xs[8][5][58];     // [ci][row][col+1pad]
    __shared__ __align__(16) float ws[8 * 9][64];    // [ci*9+tap][co]
    __shared__ __align__(16) float wsh[8][64];       // [ci][co]

    const int tid   = threadIdx.x;
    const int co_b  = blockIdx.x;   // 0..3   (64-co group)
    const int h_b   = blockIdx.y;   // 0..13  (2 output rows)
    const int n     = blockIdx.z;   // 0..31
    const int co_t  = tid & 15;             // 4 co each
    const int px_t  = (tid >> 4) & 3;       // 7 px each (pw = px_t + 4j)
    const int row_t = tid >> 6;             // output row h0+row_t

    float acc[28], ida[28], psq[7];
#pragma unroll
    for (int i = 0; i < 28; i++) { acc[i] = 0.f; ida[i] = 0.f; }
#pragma unroll
    for (int j = 0; j < 7; j++) psq[j] = 0.f;

    const float* xbase = x + (size_t)n * CI * HI * WI;
    const int gr0 = 4 * h_b - 1;    // first input row needed

    for (int ci0 = 0; ci0 < CI; ci0 += 8) {
        __syncthreads();
        // fill xs: 8 ci x 5 rows x 58 cols (zero-padded)
        for (int idx = tid; idx < 8 * 5 * 58; idx += 128) {
            int cc  = idx / 290;
            int rem = idx - cc * 290;
            int r   = rem / 58;
            int c   = rem - r * 58;
            int gr  = gr0 + r;
            int gc  = c - 1;
            float v = 0.f;
            if (gr >= 0 && gr < HI && gc >= 0 && gc < WI)
                v = xbase[((ci0 + cc) * HI + gr) * WI + gc];
            xs[cc][r][c] = v;
        }
        // fill ws (coalesced gmem, conflict-free STS)
        for (int idx = tid; idx < 8 * 9 * 64; idx += 128) {
            int rr = idx >> 6;
            int co = idx & 63;
            ws[rr][co] = g_wyat_t[(ci0 * 9 + rr) * CO + co_b * 64 + co];
        }
        // fill shortcut weights
        for (int idx = tid; idx < 8 * 64; idx += 128) {
            int cc = idx >> 6;
            int co = idx & 63;
            wsh[cc][co] = g_wsh_t[(ci0 + cc) * CO + co_b * 64 + co];
        }
        __syncthreads();

#pragma unroll
        for (int cc = 0; cc < 8; cc++) {
#pragma unroll
            for (int kh = 0; kh < 3; kh++) {
                const int r = 2 * row_t + kh;
#pragma unroll
                for (int kw = 0; kw < 3; kw++) {
                    float xv[7];
#pragma unroll
                    for (int j = 0; j < 7; j++)
                        xv[j] = xs[cc][r][2 * (px_t + 4 * j) + kw];
                    float4 w4 = *(const float4*)&ws[cc * 9 + kh * 3 + kw][co_t * 4];
#pragma unroll
                    for (int j = 0; j < 7; j++) {
                        acc[0 * 7 + j] += w4.x * xv[j];
                        acc[1 * 7 + j] += w4.y * xv[j];
                        acc[2 * 7 + j] += w4.z * xv[j];
                        acc[3 * 7 + j] += w4.w * xv[j];
                        psq[j] += xv[j] * xv[j];
                    }
                    if (kh == 1 && kw == 1) {      // center tap = 1x1 stride-2 shortcut
                        float4 s4 = *(const float4*)&wsh[cc][co_t * 4];
#pragma unroll
                        for (int j = 0; j < 7; j++) {
                            ida[0 * 7 + j] += s4.x * xv[j];
                            ida[1 * 7 + j] += s4.y * xv[j];
                            ida[2 * 7 + j] += s4.z * xv[j];
                            ida[3 * 7 + j] += s4.w * xv[j];
                        }
                    }
                }
            }
        }
    }

    // epilogue: y = scale * dot^2 / (|patch|^2 + |w|^2 - 2 dot + eps)
    const float scale = powf(16.0f / logf(257.0f), alpha[0]);
    const int h = 2 * h_b + row_t;
#pragma unroll
    for (int i = 0; i < 4; i++) {
        const int co = co_b * 64 + co_t * 4 + i;
        const float wq = g_wsq[co];
        const size_t base = (((size_t)n * CO + co) * HO + h) * WO;
#pragma unroll
        for (int j = 0; j < 7; j++) {
            const int pw = px_t + 4 * j;
            const float dot = acc[i * 7 + j];
            const float d = psq[j] + wq - 2.f * dot + EPSV;
            g_y[base + pw] = scale * dot * dot / d;
            out_id[base + pw] = ida[i * 7 + j];   // identity term, added in stage B
        }
    }
}

// ---------------- Stage B: 3x3 stride-1 conv over g_y, += identity -------
__global__ __launch_bounds__(128)
void lin_kernel(float* __restrict__ out) {
    __shared__ __align__(16) float ys[8][4][30];
    __shared__ __align__(16) float ws[8 * 9][64];

    const int tid   = threadIdx.x;
    const int co_b  = blockIdx.x;
    const int h_b   = blockIdx.y;
    const int n     = blockIdx.z;
    const int co_t  = tid & 15;
    const int px_t  = (tid >> 4) & 3;
    const int row_t = tid >> 6;

    float acc[28];
#pragma unroll
    for (int i = 0; i < 28; i++) acc[i] = 0.f;

    const int h0 = 2 * h_b;

    for (int ci0 = 0; ci0 < C2; ci0 += 8) {
        __syncthreads();
        for (int idx = tid; idx < 8 * 4 * 30; idx += 128) {
            int cc  = idx / 120;
            int rem = idx - cc * 120;
            int r   = rem / 30;
            int c   = rem - r * 30;
            int gr  = h0 - 1 + r;
            int gc  = c - 1;
            float v = 0.f;
            if (gr >= 0 && gr < HO && gc >= 0 && gc < WO)
                v = g_y[(((size_t)n * C2 + ci0 + cc) * HO + gr) * WO + gc];
            ys[cc][r][c] = v;
        }
        for (int idx = tid; idx < 8 * 9 * 64; idx += 128) {
            int rr = idx >> 6;
            int co = idx & 63;
            ws[rr][co] = g_wlin_t[(ci0 * 9 + rr) * CO + co_b * 64 + co];
        }
        __syncthreads();

#pragma unroll
        for (int cc = 0; cc < 8; cc++) {
#pragma unroll
            for (int kh = 0; kh < 3; kh++) {
                const int r = row_t + kh;
#pragma unroll
                for (int kw = 0; kw < 3; kw++) {
                    float4 w4 = *(const float4*)&ws[cc * 9 + kh * 3 + kw][co_t * 4];
#pragma unroll
                    for (int j = 0; j < 7; j++) {
                        float xv = ys[cc][r][px_t + 4 * j + kw];
                        acc[0 * 7 + j] += w4.x * xv;
                        acc[1 * 7 + j] += w4.y * xv;
                        acc[2 * 7 + j] += w4.z * xv;
                        acc[3 * 7 + j] += w4.w * xv;
                    }
                }
            }
        }
    }

    const int h = h0 + row_t;
#pragma unroll
    for (int i = 0; i < 4; i++) {
        const int co = co_b * 64 + co_t * 4 + i;
        const size_t base = (((size_t)n * CO + co) * HO + h) * WO;
#pragma unroll
        for (int j = 0; j < 7; j++) {
            const int pw = px_t + 4 * j;
            out[base + pw] = acc[i * 7 + j] + out[base + pw];  // += identity
        }
    }
}

// ---------------- launch ---------------------------------------------------
extern "C" void kernel_launch(void* const* d_in, const int* in_sizes, int n_in,
                              void* d_out, int out_size) {
    const float* x       = (const float*)d_in[0];
    const float* w_yat   = (const float*)d_in[1];
    const float* alpha   = (const float*)d_in[2];
    const float* w_lin   = (const float*)d_in[3];
    const float* w_short = (const float*)d_in[4];
    float* out = (float*)d_out;

    prep_yat<<<CI * 9, CO>>>(w_yat);
    prep_lin<<<C2 * 9, CO>>>(w_lin);
    prep_sh<<<CI, CO>>>(w_short);
    prep_wsq<<<CO, 128>>>(w_yat);

    dim3 grid(4, 14, NB);           // co-groups x row-pairs x batch
    yat_kernel<<<grid, 128>>>(x, alpha, out);
    lin_kernel<<<grid, 128>>>(out);
}

// round 6
// speedup vs baseline: 3.5093x; 3.4636x over previous
#include <cuda_runtime.h>
#include <cuda_bf16.h>
#include <cstdint>

// ---------------------------------------------------------------- constants
#define EPSV 0.007f
#define NPIX 25088              // 32*28*28 = 196 * 128
#define KA   1152
#define KB   2432               // 9*256 + 128 shortcut
#define NKA  36                 // KA/32
#define NKB  76                 // KB/32

#define ROWB      80            // padded bytes per 32-bf16 k-row (conflict-free ldmatrix)
#define STAGE_SZ  40960         // 4 arrays * 128 rows * 80B
#define OFF_ALO   10240
#define OFF_BHI   20480
#define OFF_BLO   30720
#define DYN_SMEM  (2 * STAGE_SZ)   // 81920; epilogue reuse needs 128*132*4 = 67584 <= this

// ---------------------------------------------------------------- globals
__device__ __align__(256) __nv_bfloat16 g_xhi[(size_t)32 * 56 * 56 * 128];
__device__ __align__(256) __nv_bfloat16 g_xlo[(size_t)32 * 56 * 56 * 128];
__device__ __align__(256) __nv_bfloat16 g_yhi[(size_t)NPIX * 256];
__device__ __align__(256) __nv_bfloat16 g_ylo[(size_t)NPIX * 256];
__device__ __align__(256) float g_xs2[32 * 56 * 56];
__device__ __align__(256) float g_psq[NPIX];
__device__ __align__(256) __nv_bfloat16 g_bAhi[256 * KA], g_bAlo[256 * KA];
__device__ __align__(256) __nv_bfloat16 g_bBhi[256 * KB], g_bBlo[256 * KB];
__device__ __align__(256) float g_wsq[256];

// ---------------------------------------------------------------- ptx utils
__device__ __forceinline__ uint32_t smem_u32(const void* p) {
    return (uint32_t)__cvta_generic_to_shared(p);
}
__device__ __forceinline__ void cpa16(uint32_t dst, const void* src, uint32_t sz) {
    asm volatile("cp.async.cg.shared.global [%0], [%1], 16, %2;"
                 :: "r"(dst), "l"(src), "r"(sz) : "memory");
}
#define CP_COMMIT() asm volatile("cp.async.commit_group;" ::: "memory")
#define CP_WAIT1()  asm volatile("cp.async.wait_group 1;" ::: "memory")
#define CP_WAIT0()  asm volatile("cp.async.wait_group 0;" ::: "memory")

#define LDSM4(r0, r1, r2, r3, addr) \
    asm volatile("ldmatrix.sync.aligned.m8n8.x4.shared.b16 {%0,%1,%2,%3}, [%4];" \
                 : "=r"(r0), "=r"(r1), "=r"(r2), "=r"(r3) : "r"(addr))

#define MMA16816(C, A, B0, B1) \
    asm volatile("mma.sync.aligned.m16n8k16.row.col.f32.bf16.bf16.f32 " \
                 "{%0,%1,%2,%3}, {%4,%5,%6,%7}, {%8,%9}, {%0,%1,%2,%3};" \
                 : "+f"((C)[0]), "+f"((C)[1]), "+f"((C)[2]), "+f"((C)[3]) \
                 : "r"((A)[0]), "r"((A)[1]), "r"((A)[2]), "r"((A)[3]), \
                   "r"(B0), "r"(B1))

// ---------------------------------------------------------------- prep
// x NCHW -> planar NHWC bf16 hi/lo + per-(n,h,w) channel sum of squares
__global__ __launch_bounds__(256) void prep_x(const float* __restrict__ x) {
    __shared__ float s[128][57];
    __shared__ float s2p[56][4];
    const int h = blockIdx.x, n = blockIdx.y;
    const float* xb = x + ((size_t)n * 128 * 56 + h) * 56;   // + ci*3136 + wi
    for (int idx = threadIdx.x; idx < 128 * 56; idx += 256) {
        int ci = idx / 56, wi = idx - 56 * ci;
        s[ci][wi] = xb[(size_t)ci * 3136 + wi];
    }
    __syncthreads();
    for (int idx = threadIdx.x; idx < 56 * 128; idx += 256) {
        int wi = idx >> 7, ci = idx & 127;
        float v = s[ci][wi];
        __nv_bfloat16 hb = __float2bfloat16(v);
        size_t o = ((size_t)(n * 56 + h) * 56 + wi) * 128 + ci;
        g_xhi[o] = hb;
        g_xlo[o] = __float2bfloat16(v - __bfloat162float(hb));
    }
    if (threadIdx.x < 224) {
        int wi = threadIdx.x >> 2, q = threadIdx.x & 3;
        float a = 0.f;
        for (int ci = q * 32; ci < q * 32 + 32; ci++) { float v = s[ci][wi]; a += v * v; }
        s2p[wi][q] = a;
    }
    __syncthreads();
    if (threadIdx.x < 56) {
        int wi = threadIdx.x;
        g_xs2[(n * 56 + h) * 56 + wi] = s2p[wi][0] + s2p[wi][1] + s2p[wi][2] + s2p[wi][3];
    }
}

__global__ void prep_psq() {
    const int pw = threadIdx.x, ph = blockIdx.x, n = blockIdx.y;
    float s = 0.f;
    for (int dr = -1; dr <= 1; dr++) {
        int r = 2 * ph + dr;
        if ((unsigned)r >= 56) continue;
        for (int dc = -1; dc <= 1; dc++) {
            int c = 2 * pw + dc;
            if ((unsigned)c >= 56) continue;
            s += g_xs2[(n * 56 + r) * 56 + c];
        }
    }
    g_psq[(n * 28 + ph) * 28 + pw] = s;
}

// w_yat [co][ci][3][3] -> g_bA(hi/lo)[co][k = tap*128 + ci], plus wsq
__global__ __launch_bounds__(256) void prep_wA(const float* __restrict__ w) {
    __shared__ float red[256];
    const int co = blockIdx.x;
    float acc = 0.f;
    for (int k = threadIdx.x; k < KA; k += 256) {
        int kh = k / 384, rem = k - kh * 384, kw = rem >> 7, ci = rem & 127;
        float v = w[(size_t)co * KA + ci * 9 + kh * 3 + kw];
        __nv_bfloat16 hb = __float2bfloat16(v);
        g_bAhi[(size_t)co * KA + k] = hb;
        g_bAlo[(size_t)co * KA + k] = __float2bfloat16(v - __bfloat162float(hb));
        acc += v * v;
    }
    red[threadIdx.x] = acc;
    __syncthreads();
    for (int o = 128; o > 0; o >>= 1) {
        if (threadIdx.x < o) red[threadIdx.x] += red[threadIdx.x + o];
        __syncthreads();
    }
    if (threadIdx.x == 0) g_wsq[co] = red[0];
}

// w_lin [co][256][3][3] + w_short [co][128] -> g_bB(hi/lo)[co][2432]
__global__ __launch_bounds__(256) void prep_wB(const float* __restrict__ wl,
                                               const float* __restrict__ ws) {
    const int co = blockIdx.x;
    for (int k = threadIdx.x; k < 2304; k += 256) {
        int kh = k / 768, rem = k - kh * 768, kw = rem >> 8, ci = rem & 255;
        float v = wl[(size_t)co * 2304 + ci * 9 + kh * 3 + kw];
        __nv_bfloat16 hb = __float2bfloat16(v);
        g_bBhi[(size_t)co * KB + k] = hb;
        g_bBlo[(size_t)co * KB + k] = __float2bfloat16(v - __bfloat162float(hb));
    }
    for (int k = threadIdx.x; k < 128; k += 256) {
        float v = ws[co * 128 + k];
        __nv_bfloat16 hb = __float2bfloat16(v);
        g_bBhi[(size_t)co * KB + 2304 + k] = hb;
        g_bBlo[(size_t)co * KB + 2304 + k] = __float2bfloat16(v - __bfloat162float(hb));
    }
}

// ---------------------------------------------------------------- k-block fill
// stage buffer: [A_hi][A_lo][B_hi][B_lo], 128 rows x 32 bf16, rows padded to 80B
__device__ __forceinline__ void fill_tile(int stage, int kb, uint32_t sbuf,
                                          int t, int ctaM, int ctaN) {
#pragma unroll
    for (int j = 0; j < 2; j++) {
        const int idx = t + 256 * j;
        const int row = idx >> 2;
        const int ch  = idx & 3;

        // ---- A operand row (pixel gather) ----
        const int p   = ctaM * 128 + row;
        const int n   = p / 784;
        const int rem = p - n * 784;
        const int ph  = rem / 28;
        const int pw  = rem - ph * 28;

        const __nv_bfloat16 *ah, *al;
        uint32_t ok;
        if (stage == 0) {
            int tap = kb >> 2, kh = tap / 3, kw = tap - 3 * (tap / 3);
            int ci0 = (kb & 3) * 32;
            int r = 2 * ph - 1 + kh, c = 2 * pw - 1 + kw;
            bool v = ((unsigned)r < 56) && ((unsigned)c < 56);
            size_t off = v ? ((size_t)((n * 56 + r) * 56 + c) * 128 + ci0) : 0;
            ah = g_xhi + off; al = g_xlo + off; ok = v ? 16u : 0u;
        } else if (kb < 72) {
            int tap = kb >> 3, kh = tap / 3, kw = tap - 3 * (tap / 3);
            int co0 = (kb & 7) * 32;
            int r = ph - 1 + kh, c = pw - 1 + kw;
            bool v = ((unsigned)r < 28) && ((unsigned)c < 28);
            size_t off = v ? ((size_t)((n * 28 + r) * 28 + c) * 256 + co0) : 0;
            ah = g_yhi + off; al = g_ylo + off; ok = v ? 16u : 0u;
        } else {
            int ci0 = (kb - 72) * 32;
            size_t off = (size_t)((n * 56 + 2 * ph) * 56 + 2 * pw) * 128 + ci0;
            ah = g_xhi + off; al = g_xlo + off; ok = 16u;
        }

        const uint32_t d = sbuf + row * ROWB + ch * 16;
        cpa16(d,           (const char*)ah + ch * 16, ok);
        cpa16(d + OFF_ALO, (const char*)al + ch * 16, ok);

        // ---- B operand row (weights) ----
        const int co = ctaN * 128 + row;
        const size_t bo = stage ? ((size_t)co * KB + kb * 32) : ((size_t)co * KA + kb * 32);
        const __nv_bfloat16* bh = (stage ? g_bBhi : g_bAhi) + bo;
        const __nv_bfloat16* bl = (stage ? g_bBlo : g_bAlo) + bo;
        cpa16(d + OFF_BHI, (const char*)bh + ch * 16, 16u);
        cpa16(d + OFF_BLO, (const char*)bl + ch * 16, 16u);
    }
}

// ---------------------------------------------------------------- GEMM kernel
// CTA 128 pixels x 128 co; 8 warps as 4(m) x 2(n); warp tile 32 x 64.
__global__ __launch_bounds__(256, 2)
void gemm_kernel(int stage, const float* __restrict__ alpha, float* __restrict__ out) {
    extern __shared__ char dsm[];
    __shared__ float s_psq[128];
    __shared__ float s_wsq[128];

    const int t    = threadIdx.x;
    const int lane = t & 31;
    const int w    = t >> 5;
    const int wm   = w & 3;         // m32 block
    const int wn   = w >> 2;        // n64 block
    const int ctaM = blockIdx.x;
    const int ctaN = blockIdx.y;
    const uint32_t sdyn = smem_u32(dsm);

    if (stage == 0) {
        if (t < 128) {
            s_psq[t] = g_psq[ctaM * 128 + t];
            s_wsq[t] = g_wsq[ctaN * 128 + t];
        }
    }

    float acc[2][8][4];
#pragma unroll
    for (int a = 0; a < 2; a++)
#pragma unroll
        for (int b = 0; b < 8; b++)
#pragma unroll
            for (int c = 0; c < 4; c++) acc[a][b][c] = 0.f;

    const uint32_t aOff = (uint32_t)(wm * 32 + (lane & 15)) * ROWB + (lane >> 4) * 16;
    const uint32_t bOff = (uint32_t)(wn * 64 + (lane & 7) + ((lane >> 4) << 3)) * ROWB
                        + ((lane >> 3) & 1) * 16;

    const int NK = stage ? NKB : NKA;

    fill_tile(stage, 0, sdyn, t, ctaM, ctaN);
    CP_COMMIT();

    for (int kb = 0; kb < NK; kb++) {
        if (kb + 1 < NK) {
            fill_tile(stage, kb + 1, sdyn + ((kb + 1) & 1) * STAGE_SZ, t, ctaM, ctaN);
            CP_COMMIT();
            CP_WAIT1();
        } else {
            CP_WAIT0();
        }
        __syncthreads();

        const uint32_t sb = sdyn + (kb & 1) * STAGE_SZ;
#pragma unroll
        for (int kc = 0; kc < 2; kc++) {
            const uint32_t kByte = kc * 32;
            uint32_t ah[2][4], alr[2][4];
#pragma unroll
            for (int im = 0; im < 2; im++) {
                uint32_t addr = sb + aOff + im * (16 * ROWB) + kByte;
                LDSM4(ah[im][0], ah[im][1], ah[im][2], ah[im][3], addr);
                LDSM4(alr[im][0], alr[im][1], alr[im][2], alr[im][3], addr + OFF_ALO);
            }
#pragma unroll
            for (int ip = 0; ip < 4; ip++) {
                uint32_t baddr = sb + OFF_BHI + bOff + ip * (16 * ROWB) + kByte;
                uint32_t bh0, bh1, bh2, bh3, bl0, bl1, bl2, bl3;
                LDSM4(bh0, bh1, bh2, bh3, baddr);
                LDSM4(bl0, bl1, bl2, bl3, baddr + (OFF_BLO - OFF_BHI));
#pragma unroll
                for (int im = 0; im < 2; im++) {
                    MMA16816(acc[im][2 * ip],     ah[im],  bh0, bh1);
                    MMA16816(acc[im][2 * ip],     ah[im],  bl0, bl1);
                    MMA16816(acc[im][2 * ip],     alr[im], bh0, bh1);
                    MMA16816(acc[im][2 * ip + 1], ah[im],  bh2, bh3);
                    MMA16816(acc[im][2 * ip + 1], ah[im],  bl2, bl3);
                    MMA16816(acc[im][2 * ip + 1], alr[im], bh2, bh3);
                }
            }
        }
        __syncthreads();
    }

    // ---------------- epilogue ----------------
    if (stage == 0) {
        const float scale = powf(16.0f / logf(257.0f), alpha[0]);
#pragma unroll
        for (int im = 0; im < 2; im++) {
#pragma unroll
            for (int ip8 = 0; ip8 < 8; ip8++) {
                const int cl = wn * 64 + ip8 * 8 + 2 * (lane & 3);
                const float wq0 = s_wsq[cl], wq1 = s_wsq[cl + 1];
                const float* c = acc[im][ip8];
#pragma unroll
                for (int s = 0; s < 2; s++) {
                    const int pl = wm * 32 + im * 16 + (lane >> 2) + 8 * s;
                    const int p  = ctaM * 128 + pl;
                    const float psqv = s_psq[pl];
                    const float f0 = c[2 * s], f1 = c[2 * s + 1];
                    const float y0 = scale * f0 * f0 / (psqv + wq0 - 2.f * f0 + EPSV);
                    const float y1 = scale * f1 * f1 / (psqv + wq1 - 2.f * f1 + EPSV);
                    __nv_bfloat16 h0 = __float2bfloat16(y0);
                    __nv_bfloat16 h1 = __float2bfloat16(y1);
                    const float l0 = y0 - __bfloat162float(h0);
                    const float l1 = y1 - __bfloat162float(h1);
                    const size_t oi = (size_t)p * 128 + ((ctaN * 128 + cl) >> 1);
                    ((uint32_t*)g_yhi)[oi] = (uint32_t)__bfloat16_as_ushort(h0) |
                                             ((uint32_t)__bfloat16_as_ushort(h1) << 16);
                    ((uint32_t*)g_ylo)[oi] =
                        (uint32_t)__bfloat16_as_ushort(__float2bfloat16(l0)) |
                        ((uint32_t)__bfloat16_as_ushort(__float2bfloat16(l1)) << 16);
                }
            }
        }
    } else {
        // transpose through smem for coalesced NCHW stores
        __syncthreads();
        float* sy = (float*)dsm;
#pragma unroll
        for (int im = 0; im < 2; im++) {
#pragma unroll
            for (int ip8 = 0; ip8 < 8; ip8++) {
                const int cl = wn * 64 + ip8 * 8 + 2 * (lane & 3);
                const float* c = acc[im][ip8];
#pragma unroll
                for (int s = 0; s < 2; s++) {
                    const int pl = wm * 32 + im * 16 + (lane >> 2) + 8 * s;
                    sy[cl * 132 + pl]       = c[2 * s];
                    sy[(cl + 1) * 132 + pl] = c[2 * s + 1];
                }
            }
        }
        __syncthreads();
        for (int i = t; i < 128 * 128; i += 256) {
            const int col = i >> 7, q = i & 127;
            const int p = ctaM * 128 + q;
            const int n = p / 784, rem = p - n * 784;
            out[(size_t)n * 200704 + (size_t)(ctaN * 128 + col) * 784 + rem] =
                sy[col * 132 + q];
        }
    }
}

// ---------------------------------------------------------------- launch
extern "C" void kernel_launch(void* const* d_in, const int* in_sizes, int n_in,
                              void* d_out, int out_size) {
    const float* x       = (const float*)d_in[0];
    const float* w_yat   = (const float*)d_in[1];
    const float* alpha   = (const float*)d_in[2];
    const float* w_lin   = (const float*)d_in[3];
    const float* w_short = (const float*)d_in[4];
    float* out = (float*)d_out;

    cudaFuncSetAttribute(gemm_kernel, cudaFuncAttributeMaxDynamicSharedMemorySize, DYN_SMEM);

    prep_x  <<<dim3(56, 32), 256>>>(x);
    prep_psq<<<dim3(28, 32), 28>>>();
    prep_wA <<<256, 256>>>(w_yat);
    prep_wB <<<256, 256>>>(w_lin, w_short);

    dim3 grid(196, 2);
    gemm_kernel<<<grid, 256, DYN_SMEM>>>(0, alpha, out);   // YAT -> g_yhi/g_ylo
    gemm_kernel<<<grid, 256, DYN_SMEM>>>(1, alpha, out);   // lin + shortcut -> out
}